// round 11
// baseline (speedup 1.0000x reference)
#include <cuda_runtime.h>
#include <cuda_bf16.h>
#include <cuda_fp16.h>
#include <cuda_fp8.h>
#include <cstdint>

#define T_ 4
#define B_ 16
#define C_ 384
#define N_ 1024
#define TB_STRIDE (B_*C_*N_)
#define CAP_ 48
#define WQ8_ROW 384   // bytes per fp8 row

// ---------------- scratch (device globals; no allocation) ----------------
__device__ unsigned int  g_mask[(size_t)T_*B_*N_*12];     // 3 MB channel masks
__device__ __align__(16) unsigned char g_wq8[C_*C_];      // wq8[c][o] e4m3 (147 KB)
__device__ __align__(16) float         g_wpT[C_*C_];      // wpT[c][o] fp32
__device__ __align__(16) float g_qinv[C_];
__device__ __align__(16) float g_qadd[C_];
__device__ __align__(16) float g_pinv[C_];
__device__ __align__(16) float g_pc[C_];

// e4m3 pair (low 16 bits) -> half2 via HW cvt
__device__ __forceinline__ __half2 cvt8(unsigned v) {
    unsigned r;
    unsigned short s = (unsigned short)v;
    asm("cvt.rn.f16x2.e4m3x2 %0, %1;" : "=r"(r) : "h"(s));
    return *reinterpret_cast<__half2*>(&r);
}

// ---------------- K0+K1 merged: LIF-pack (0..767) + weight-prep (768..1919) ----------------
#define LP_BLOCKS 768          // (N/256=4) * (C/32=12) * B=16
#define PREP_BLOCKS 1152       // C*C / 128

__global__ void __launch_bounds__(128) k_front(
    const float* __restrict__ x,
    const float* __restrict__ wq, const float* __restrict__ wp,
    const float* __restrict__ qg, const float* __restrict__ qb,
    const float* __restrict__ qm, const float* __restrict__ qv,
    const float* __restrict__ pg, const float* __restrict__ pb,
    const float* __restrict__ pm, const float* __restrict__ pv,
    const float* __restrict__ bp)
{
    const int bx = blockIdx.x;
    if (bx < LP_BLOCKS) {
        // ---- LIF(x) + bit-pack: thread owns 2 consecutive n, 32 channels, all t ----
        const int nq = bx & 3;
        const int cy = (bx >> 2) % 12;
        const int b  = bx / 48;
        const int n0 = nq * 256 + threadIdx.x * 2;
        const int c0 = cy * 32;

        unsigned m[T_][2];
#pragma unroll
        for (int t = 0; t < T_; t++) { m[t][0] = 0u; m[t][1] = 0u; }

#pragma unroll 4
        for (int k = 0; k < 32; k++) {
            const float* px = x + ((size_t)b * C_ + c0 + k) * N_ + n0;
            float v0 = 0.f, v1 = 0.f;
#pragma unroll
            for (int t = 0; t < T_; t++) {
                float2 xt = *(const float2*)(px + (size_t)t * TB_STRIDE);
                float h0 = v0 + (xt.x - v0) * 0.5f;
                float h1 = v1 + (xt.y - v1) * 0.5f;
                bool s0 = h0 >= 1.0f, s1 = h1 >= 1.0f;
                v0 = s0 ? 0.f : h0;  v1 = s1 ? 0.f : h1;
                m[t][0] |= (s0 ? 1u : 0u) << k;
                m[t][1] |= (s1 ? 1u : 0u) << k;
            }
        }

#pragma unroll
        for (int t = 0; t < T_; t++)
#pragma unroll
            for (int j = 0; j < 2; j++)
                g_mask[(((size_t)t * B_ + b) * N_ + n0 + j) * 12 + cy] = m[t][j];
    } else {
        // ---- weight transpose (wq -> fp8, wp -> fp32) + bn constant folding ----
        int i = (bx - LP_BLOCKS) * 128 + threadIdx.x;
        if (i < C_ * C_) {
            int o = i / C_;
            int c = i - o * C_;
            g_wq8[c * C_ + o] = __nv_cvt_float_to_fp8(wq[i], __NV_SATFINITE, __NV_E4M3);
            g_wpT[c * C_ + o] = wp[i];
        }
        if (i < C_) {
            float iv = qg[i] / sqrtf(qv[i] + 1e-5f);
            g_qinv[i] = iv;
            g_qadd[i] = qb[i] - qm[i] * iv;
            float iv2 = pg[i] / sqrtf(pv[i] + 1e-5f);
            g_pinv[i] = iv2;
            g_pc[i]   = pb[i] - pm[i] * iv2 + bp[i] * iv2;
        }
    }
}

// ---------------- K2: warp-per-n fused sparse pipeline (fp8 phase-1) ----------------
// block = (b, 8 n); 256 threads = 8 warps; warp w owns n = n0 + w.
// lane owns 12 outputs: o in [8l, 8l+8) ("lo") and [256+4l, 256+4l+4) ("hi").
__global__ void __launch_bounds__(256) k_main(
    const unsigned char* __restrict__ ak, const unsigned char* __restrict__ av,
    float* __restrict__ out)
{
    __shared__ float        stage[8 * C_];            // [j=n_local][o], one t at a time
    __shared__ unsigned int lists[8 * T_ * CAP_];     // byte offsets c*384
    __shared__ unsigned int qmaskS[8 * T_ * 12];

    const int bg   = blockIdx.x;
    const int n0   = (bg & 127) * 8;
    const int b    = bg >> 7;
    const int tid  = threadIdx.x;
    const int lane = tid & 31;
    const int warp = tid >> 5;

    // ---- cooperative mask load for all 8 n ----
    for (int i = tid; i < 8 * T_ * 12; i += 256) {
        int w = i / (T_ * 12);
        int r = i - w * (T_ * 12);
        int t = r / 12, wd = r - t * 12;
        qmaskS[i] = g_mask[(((size_t)t * B_ + b) * N_ + n0 + w) * 12 + wd];
    }
    __syncthreads();

    // ---- per-warp decode: masks -> compact byte-offset lists ----
    int Kt[T_];
#pragma unroll
    for (int t = 0; t < T_; t++) {
        const unsigned int* mw = qmaskS + (warp * T_ + t) * 12;
        unsigned int* lst = lists + (warp * T_ + t) * CAP_;
        int base = 0;
#pragma unroll
        for (int w12 = 0; w12 < 12; w12++) {
            unsigned m = mw[w12];
            if (m & (1u << lane)) {
                int pos = base + __popc(m & ((1u << lane) - 1));
                if (pos < CAP_) lst[pos] = (unsigned)(w12 * 32 + lane) * WQ8_ROW;
            }
            base += __popc(m);
        }
        Kt[t] = base;
    }
    __syncwarp();

    // ---- phase 1: sparse q accumulate, fp8 -> fp16 ----
    const unsigned char* wq_lo = g_wq8 + 8 * lane;        // 8 outputs, uint2
    const unsigned char* wq_hi = g_wq8 + 256 + 4 * lane;  // 4 outputs, uint

    __half2 acc[T_][6];
#pragma unroll
    for (int t = 0; t < T_; t++)
#pragma unroll
        for (int j = 0; j < 6; j++) acc[t][j] = __half2(__float2half(0.f), __float2half(0.f));

#pragma unroll
    for (int t = 0; t < T_; t++) {
        const int K = Kt[t];
        const unsigned int* lst = lists + (warp * T_ + t) * CAP_;
        if (K <= CAP_) {
            int i = 0;
            for (; i + 4 <= K; i += 4) {
                unsigned f0 = lst[i], f1 = lst[i + 1], f2 = lst[i + 2], f3 = lst[i + 3];
                uint2 A0 = *(const uint2*)(wq_lo + f0);
                uint2 A1 = *(const uint2*)(wq_lo + f1);
                uint2 A2 = *(const uint2*)(wq_lo + f2);
                uint2 A3 = *(const uint2*)(wq_lo + f3);
                unsigned H0 = *(const unsigned*)(wq_hi + f0);
                unsigned H1 = *(const unsigned*)(wq_hi + f1);
                unsigned H2 = *(const unsigned*)(wq_hi + f2);
                unsigned H3 = *(const unsigned*)(wq_hi + f3);
                // tree-reduce 4 channels per accumulator slot
                acc[t][0] = __hadd2(acc[t][0], __hadd2(__hadd2(cvt8(A0.x), cvt8(A1.x)),
                                                       __hadd2(cvt8(A2.x), cvt8(A3.x))));
                acc[t][1] = __hadd2(acc[t][1], __hadd2(__hadd2(cvt8(A0.x >> 16), cvt8(A1.x >> 16)),
                                                       __hadd2(cvt8(A2.x >> 16), cvt8(A3.x >> 16))));
                acc[t][2] = __hadd2(acc[t][2], __hadd2(__hadd2(cvt8(A0.y), cvt8(A1.y)),
                                                       __hadd2(cvt8(A2.y), cvt8(A3.y))));
                acc[t][3] = __hadd2(acc[t][3], __hadd2(__hadd2(cvt8(A0.y >> 16), cvt8(A1.y >> 16)),
                                                       __hadd2(cvt8(A2.y >> 16), cvt8(A3.y >> 16))));
                acc[t][4] = __hadd2(acc[t][4], __hadd2(__hadd2(cvt8(H0), cvt8(H1)),
                                                       __hadd2(cvt8(H2), cvt8(H3))));
                acc[t][5] = __hadd2(acc[t][5], __hadd2(__hadd2(cvt8(H0 >> 16), cvt8(H1 >> 16)),
                                                       __hadd2(cvt8(H2 >> 16), cvt8(H3 >> 16))));
            }
            for (; i < K; i++) {
                unsigned off = lst[i];
                uint2 A = *(const uint2*)(wq_lo + off);
                unsigned H = *(const unsigned*)(wq_hi + off);
                acc[t][0] = __hadd2(acc[t][0], cvt8(A.x));
                acc[t][1] = __hadd2(acc[t][1], cvt8(A.x >> 16));
                acc[t][2] = __hadd2(acc[t][2], cvt8(A.y));
                acc[t][3] = __hadd2(acc[t][3], cvt8(A.y >> 16));
                acc[t][4] = __hadd2(acc[t][4], cvt8(H));
                acc[t][5] = __hadd2(acc[t][5], cvt8(H >> 16));
            }
        } else {
            // exact fallback: ffs scan of mask words
            const unsigned int* mw = qmaskS + (warp * T_ + t) * 12;
#pragma unroll
            for (int w12 = 0; w12 < 12; w12++) {
                unsigned m = mw[w12];
                while (m) {
                    int bit = __ffs((int)m) - 1;
                    m &= m - 1;
                    unsigned off = (unsigned)(w12 * 32 + bit) * WQ8_ROW;
                    uint2 A = *(const uint2*)(wq_lo + off);
                    unsigned H = *(const unsigned*)(wq_hi + off);
                    acc[t][0] = __hadd2(acc[t][0], cvt8(A.x));
                    acc[t][1] = __hadd2(acc[t][1], cvt8(A.x >> 16));
                    acc[t][2] = __hadd2(acc[t][2], cvt8(A.y));
                    acc[t][3] = __hadd2(acc[t][3], cvt8(A.y >> 16));
                    acc[t][4] = __hadd2(acc[t][4], cvt8(H));
                    acc[t][5] = __hadd2(acc[t][5], cvt8(H >> 16));
                }
            }
        }
    }

    // ---- phase 2a: branch-free q_bn -> q_lif scan -> 12-bit spike mask per lane ----
    const int n = n0 + warp;
    unsigned smask[T_] = {0u, 0u, 0u, 0u};
    {
        // lo: 8 outputs at 8*lane
        float qiL[8], qaL[8];
        *(float4*)(qiL)     = *(const float4*)(g_qinv + 8 * lane);
        *(float4*)(qiL + 4) = *(const float4*)(g_qinv + 8 * lane + 4);
        *(float4*)(qaL)     = *(const float4*)(g_qadd + 8 * lane);
        *(float4*)(qaL + 4) = *(const float4*)(g_qadd + 8 * lane + 4);
#pragma unroll
        for (int jj = 0; jj < 8; jj++) {
            float v = 0.0f;
#pragma unroll
            for (int t = 0; t < T_; t++) {
                __half2 pr = acc[t][jj >> 1];
                float qf = (jj & 1) ? __high2float(pr) : __low2float(pr);
                float qn = fmaf(qf, qiL[jj], qaL[jj]);
                float h = v + (qn - v) * 0.5f;
                bool s = (h >= 1.0f);
                v = s ? 0.0f : h;
                smask[t] |= (s ? 1u : 0u) << jj;
            }
        }
        // hi: 4 outputs at 256 + 4*lane
        float qiH[4], qaH[4];
        *(float4*)(qiH) = *(const float4*)(g_qinv + 256 + 4 * lane);
        *(float4*)(qaH) = *(const float4*)(g_qadd + 256 + 4 * lane);
#pragma unroll
        for (int jj = 0; jj < 4; jj++) {
            float v = 0.0f;
#pragma unroll
            for (int t = 0; t < T_; t++) {
                __half2 pr = acc[t][4 + (jj >> 1)];
                float qf = (jj & 1) ? __high2float(pr) : __low2float(pr);
                float qn = fmaf(qf, qiH[jj], qaH[jj]);
                float h = v + (qn - v) * 0.5f;
                bool s = (h >= 1.0f);
                v = s ? 0.0f : h;
                smask[t] |= (s ? 1u : 0u) << (8 + jj);
            }
        }
    }

    // ---- phase 2b: attn AND, one guarded region per t ----
    unsigned rmask[T_];
#pragma unroll
    for (int t = 0; t < T_; t++) {
        rmask[t] = 0u;
        if (__any_sync(0xffffffffu, smask[t] != 0u)) {
            unsigned sm = smask[t];
            const size_t base_t = (((size_t)t * B_ + b) * C_) * (size_t)N_ + n;
            while (sm) {
                int j = __ffs((int)sm) - 1;
                sm &= sm - 1;
                int o = (j < 8) ? (8 * lane + j) : (256 + 4 * lane + (j - 8));
                size_t idx = base_t + (size_t)o * N_;
                if (ak[idx] && av[idx]) rmask[t] |= 1u << j;
            }
        }
    }

    // ---- per t: phase 3 (usually skipped), epilogue bn, stage, flush ----
#pragma unroll 1
    for (int t = 0; t < T_; t++) {
        float oa[12];
#pragma unroll
        for (int j = 0; j < 12; j++) oa[j] = 0.0f;

        if (__any_sync(0xffffffffu, rmask[t] != 0u)) {
#pragma unroll 1
            for (int wbit = 0; wbit < 12; wbit++) {
                unsigned mb = __ballot_sync(0xffffffffu, (rmask[t] >> wbit) & 1u);
                while (mb) {
                    int l2 = __ffs((int)mb) - 1;
                    mb &= mb - 1;
                    int c = (wbit < 8) ? (8 * l2 + wbit) : (256 + 4 * l2 + (wbit - 8));
                    const float* row = g_wpT + c * C_;
                    float4 w0 = *(const float4*)(row + 8 * lane);
                    float4 w1 = *(const float4*)(row + 8 * lane + 4);
                    float4 w2 = *(const float4*)(row + 256 + 4 * lane);
                    oa[0] += w0.x; oa[1] += w0.y; oa[2]  += w0.z; oa[3]  += w0.w;
                    oa[4] += w1.x; oa[5] += w1.y; oa[6]  += w1.z; oa[7]  += w1.w;
                    oa[8] += w2.x; oa[9] += w2.y; oa[10] += w2.z; oa[11] += w2.w;
                }
            }
        }

        // epilogue: y = oa*pinv + pc, staged as [j=warp][o]
        {
            const int o0 = 8 * lane;
            float4 piA = *(const float4*)(g_pinv + o0);
            float4 piB = *(const float4*)(g_pinv + o0 + 4);
            float4 pcA = *(const float4*)(g_pc + o0);
            float4 pcB = *(const float4*)(g_pc + o0 + 4);
            float4 y0, y1;
            y0.x = oa[0] * piA.x + pcA.x;  y0.y = oa[1] * piA.y + pcA.y;
            y0.z = oa[2] * piA.z + pcA.z;  y0.w = oa[3] * piA.w + pcA.w;
            y1.x = oa[4] * piB.x + pcB.x;  y1.y = oa[5] * piB.y + pcB.y;
            y1.z = oa[6] * piB.z + pcB.z;  y1.w = oa[7] * piB.w + pcB.w;
            float* sp = stage + warp * C_ + o0;
            *(float4*)sp = y0;
            *(float4*)(sp + 4) = y1;

            const int o1 = 256 + 4 * lane;
            float4 piC = *(const float4*)(g_pinv + o1);
            float4 pcC = *(const float4*)(g_pc + o1);
            float4 z0;
            z0.x = oa[8]  * piC.x + pcC.x;  z0.y = oa[9]  * piC.y + pcC.y;
            z0.z = oa[10] * piC.z + pcC.z;  z0.w = oa[11] * piC.w + pcC.w;
            *(float4*)(stage + warp * C_ + o1) = z0;
        }

        // flush t: stage[j][o] -> out[t][b][o][n0..n0+8)
        __syncthreads();
        for (int o = tid; o < C_; o += 256) {
            const float* sp = stage + o;
            float4 u, w;
            u.x = sp[0 * C_]; u.y = sp[1 * C_]; u.z = sp[2 * C_]; u.w = sp[3 * C_];
            w.x = sp[4 * C_]; w.y = sp[5 * C_]; w.z = sp[6 * C_]; w.w = sp[7 * C_];
            float* dst = out + (((size_t)t * B_ + b) * C_ + o) * (size_t)N_ + n0;
            *(float4*)dst = u;
            *(float4*)(dst + 4) = w;
        }
        __syncthreads();
    }
}

// ---------------- launch ----------------
extern "C" void kernel_launch(void* const* d_in, const int* in_sizes, int n_in,
                              void* d_out, int out_size) {
    const float*         x  = (const float*)d_in[0];
    const unsigned char* ak = (const unsigned char*)d_in[1];
    const unsigned char* av = (const unsigned char*)d_in[2];
    const float*         wq = (const float*)d_in[3];
    const float*         qg = (const float*)d_in[4];
    const float*         qb = (const float*)d_in[5];
    const float*         qm = (const float*)d_in[6];
    const float*         qv = (const float*)d_in[7];
    const float*         wp = (const float*)d_in[8];
    const float*         bp = (const float*)d_in[9];
    const float*         pg = (const float*)d_in[10];
    const float*         pb = (const float*)d_in[11];
    const float*         pm = (const float*)d_in[12];
    const float*         pv = (const float*)d_in[13];
    float* out = (float*)d_out;

    (void)in_sizes; (void)n_in; (void)out_size;

    k_front<<<LP_BLOCKS + PREP_BLOCKS, 128>>>(x, wq, wp, qg, qb, qm, qv, pg, pb, pm, pv, bp);
    k_main<<<B_ * 128, 256>>>(ak, av, out);
}

// round 12
// speedup vs baseline: 1.0796x; 1.0796x over previous
#include <cuda_runtime.h>
#include <cuda_bf16.h>
#include <cstdint>

#define T_ 4
#define B_ 16
#define C_ 384
#define N_ 1024
#define TB_STRIDE (B_*C_*N_)
#define CAP_ 48
#define WQ_ROW 768                 // bytes per bf16 row
#define ZOFF ((unsigned)(C_ * WQ_ROW))   // zero-row byte offset

// ---------------- scratch (device globals; no allocation) ----------------
__device__ unsigned int  g_mask[(size_t)T_*B_*N_*12];          // 3 MB channel masks
__device__ __align__(16) __nv_bfloat16 g_wqT[(C_ + 1) * C_];   // wqT[c][o] bf16 + zero row
__device__ __align__(16) float         g_wpT[C_*C_];           // wpT[c][o] fp32
__device__ __align__(16) float g_qinv[C_];
__device__ __align__(16) float g_qadd[C_];
__device__ __align__(16) float g_pinv[C_];
__device__ __align__(16) float g_pc[C_];

// ---------------- K0+K1 merged ----------------
#define LP_BLOCKS 768          // (N/256=4) * (C/32=12) * B=16, 256 threads, 1 n/thread
#define PREP_BLOCKS 576        // C*C / 256

__global__ void __launch_bounds__(256) k_front(
    const float* __restrict__ x,
    const float* __restrict__ wq, const float* __restrict__ wp,
    const float* __restrict__ qg, const float* __restrict__ qb,
    const float* __restrict__ qm, const float* __restrict__ qv,
    const float* __restrict__ pg, const float* __restrict__ pb,
    const float* __restrict__ pm, const float* __restrict__ pv,
    const float* __restrict__ bp)
{
    const int bx = blockIdx.x;
    if (bx < LP_BLOCKS) {
        // ---- LIF(x) + bit-pack: thread owns 1 n, 32 channels, all t ----
        const int nq = bx & 3;
        const int cy = (bx >> 2) % 12;
        const int b  = bx / 48;
        const int n  = nq * 256 + threadIdx.x;
        const int c0 = cy * 32;

        unsigned m[T_];
#pragma unroll
        for (int t = 0; t < T_; t++) m[t] = 0u;

#pragma unroll 4
        for (int k = 0; k < 32; k++) {
            const float* px = x + ((size_t)b * C_ + c0 + k) * N_ + n;
            float v = 0.f;
#pragma unroll
            for (int t = 0; t < T_; t++) {
                float xt = px[(size_t)t * TB_STRIDE];
                float h = v + (xt - v) * 0.5f;
                bool  s = (h >= 1.0f);
                v = s ? 0.f : h;
                m[t] |= (s ? 1u : 0u) << k;
            }
        }

#pragma unroll
        for (int t = 0; t < T_; t++)
            g_mask[(((size_t)t * B_ + b) * N_ + n) * 12 + cy] = m[t];
    } else {
        // ---- weight transpose + zero row + bn constant folding ----
        int i = (bx - LP_BLOCKS) * 256 + threadIdx.x;
        if (i < C_ * C_) {
            int o = i / C_;
            int c = i - o * C_;
            g_wqT[c * C_ + o] = __float2bfloat16(wq[i]);
            g_wpT[c * C_ + o] = wp[i];
        }
        if (i < C_) {
            g_wqT[C_ * C_ + i] = __float2bfloat16(0.0f);   // zero row for list padding
            float iv = qg[i] / sqrtf(qv[i] + 1e-5f);
            g_qinv[i] = iv;
            g_qadd[i] = qb[i] - qm[i] * iv;
            float iv2 = pg[i] / sqrtf(pv[i] + 1e-5f);
            g_pinv[i] = iv2;
            g_pc[i]   = pb[i] - pm[i] * iv2 + bp[i] * iv2;
        }
    }
}

// ---------------- K2: warp-per-n fused sparse pipeline ----------------
// block = (b, 8 n); 256 threads = 8 warps; warp w owns n = n0 + w.
// lane owns 12 outputs: o in [8l, 8l+8) ("lo") and [256+4l, 256+4l+4) ("hi"). Uniform lanes.
__global__ void __launch_bounds__(256, 5) k_main(
    const unsigned char* __restrict__ ak, const unsigned char* __restrict__ av,
    float* __restrict__ out)
{
    __shared__ float        stage[8 * C_];            // [j=n_local][o], one t at a time
    __shared__ unsigned int lists[8 * T_ * CAP_];     // byte offsets c*768, zero-row padded
    __shared__ unsigned int qmaskS[8 * T_ * 12];

    const int bg   = blockIdx.x;
    const int n0   = (bg & 127) * 8;
    const int b    = bg >> 7;
    const int tid  = threadIdx.x;
    const int lane = tid & 31;
    const int warp = tid >> 5;

    // ---- cooperative mask load for all 8 n ----
    for (int i = tid; i < 8 * T_ * 12; i += 256) {
        int w = i / (T_ * 12);
        int r = i - w * (T_ * 12);
        int t = r / 12, wd = r - t * 12;
        qmaskS[i] = g_mask[(((size_t)t * B_ + b) * N_ + n0 + w) * 12 + wd];
    }
    __syncthreads();

    // ---- per-warp decode: masks -> compact byte-offset lists, padded to x4 ----
    int Kt[T_];
#pragma unroll
    for (int t = 0; t < T_; t++) {
        const unsigned int* mw = qmaskS + (warp * T_ + t) * 12;
        unsigned int* lst = lists + (warp * T_ + t) * CAP_;
        int base = 0;
#pragma unroll
        for (int w12 = 0; w12 < 12; w12++) {
            unsigned m = mw[w12];
            if (m & (1u << lane)) {
                int pos = base + __popc(m & ((1u << lane) - 1));
                if (pos < CAP_) lst[pos] = (unsigned)(w12 * 32 + lane) * WQ_ROW;
            }
            base += __popc(m);
        }
        // pad to multiple of 4 with zero-row offset
        int pad = (4 - (base & 3)) & 3;
        if (lane < pad && base + lane < CAP_) lst[base + lane] = ZOFF;
        Kt[t] = base;
    }
    __syncwarp();

    // ---- phase 1: sparse q accumulate in bf16x2, unconditional unroll-4 ----
    const char* wq_lo = (const char*)g_wqT + 16 * lane;        // 8 outputs, uint4
    const char* wq_hi = (const char*)g_wqT + 512 + 8 * lane;   // 4 outputs, uint2

    __nv_bfloat162 acc[T_][6];
#pragma unroll
    for (int t = 0; t < T_; t++)
#pragma unroll
        for (int j = 0; j < 6; j++) acc[t][j] = __float2bfloat162_rn(0.0f);

#pragma unroll
    for (int t = 0; t < T_; t++) {
        const int K = Kt[t];
        const unsigned int* lst = lists + (warp * T_ + t) * CAP_;
        if (K <= CAP_ - 3) {
            const int K4 = (K + 3) & ~3;
            for (int i = 0; i < K4; i += 4) {
                unsigned f0 = lst[i], f1 = lst[i + 1], f2 = lst[i + 2], f3 = lst[i + 3];
                uint4 A0 = *(const uint4*)(wq_lo + f0);
                uint4 A1 = *(const uint4*)(wq_lo + f1);
                uint4 A2 = *(const uint4*)(wq_lo + f2);
                uint4 A3 = *(const uint4*)(wq_lo + f3);
                uint2 H0 = *(const uint2*)(wq_hi + f0);
                uint2 H1 = *(const uint2*)(wq_hi + f1);
                uint2 H2 = *(const uint2*)(wq_hi + f2);
                uint2 H3 = *(const uint2*)(wq_hi + f3);
                const __nv_bfloat162* a0 = (const __nv_bfloat162*)&A0;
                const __nv_bfloat162* a1 = (const __nv_bfloat162*)&A1;
                const __nv_bfloat162* a2 = (const __nv_bfloat162*)&A2;
                const __nv_bfloat162* a3 = (const __nv_bfloat162*)&A3;
#pragma unroll
                for (int j = 0; j < 4; j++) {
                    __nv_bfloat162 u = __hadd2(__hadd2(a0[j], a1[j]), __hadd2(a2[j], a3[j]));
                    acc[t][j] = __hadd2(acc[t][j], u);
                }
                const __nv_bfloat162* h0 = (const __nv_bfloat162*)&H0;
                const __nv_bfloat162* h1 = (const __nv_bfloat162*)&H1;
                const __nv_bfloat162* h2 = (const __nv_bfloat162*)&H2;
                const __nv_bfloat162* h3 = (const __nv_bfloat162*)&H3;
#pragma unroll
                for (int j = 0; j < 2; j++) {
                    __nv_bfloat162 u = __hadd2(__hadd2(h0[j], h1[j]), __hadd2(h2[j], h3[j]));
                    acc[t][4 + j] = __hadd2(acc[t][4 + j], u);
                }
            }
        } else {
            // exact fallback: ffs scan of mask words
            const unsigned int* mw = qmaskS + (warp * T_ + t) * 12;
#pragma unroll
            for (int w12 = 0; w12 < 12; w12++) {
                unsigned m = mw[w12];
                while (m) {
                    int bit = __ffs((int)m) - 1;
                    m &= m - 1;
                    unsigned off = (unsigned)(w12 * 32 + bit) * WQ_ROW;
                    uint4 A = *(const uint4*)(wq_lo + off);
                    uint2 H = *(const uint2*)(wq_hi + off);
                    const __nv_bfloat162* a = (const __nv_bfloat162*)&A;
                    const __nv_bfloat162* h = (const __nv_bfloat162*)&H;
#pragma unroll
                    for (int j = 0; j < 4; j++) acc[t][j] = __hadd2(acc[t][j], a[j]);
#pragma unroll
                    for (int j = 0; j < 2; j++) acc[t][4 + j] = __hadd2(acc[t][4 + j], h[j]);
                }
            }
        }
    }

    // ---- phase 2a: branch-free q_bn -> q_lif scan -> 12-bit spike mask per lane ----
    const int n = n0 + warp;
    unsigned smask[T_] = {0u, 0u, 0u, 0u};
    {
        float qiL[8], qaL[8];
        *(float4*)(qiL)     = *(const float4*)(g_qinv + 8 * lane);
        *(float4*)(qiL + 4) = *(const float4*)(g_qinv + 8 * lane + 4);
        *(float4*)(qaL)     = *(const float4*)(g_qadd + 8 * lane);
        *(float4*)(qaL + 4) = *(const float4*)(g_qadd + 8 * lane + 4);
#pragma unroll
        for (int jj = 0; jj < 8; jj++) {
            float v = 0.0f;
#pragma unroll
            for (int t = 0; t < T_; t++) {
                __nv_bfloat162 pr = acc[t][jj >> 1];
                float qf = (jj & 1) ? __high2float(pr) : __low2float(pr);
                float qn = fmaf(qf, qiL[jj], qaL[jj]);
                float h = v + (qn - v) * 0.5f;
                bool s = (h >= 1.0f);
                v = s ? 0.0f : h;
                smask[t] |= (s ? 1u : 0u) << jj;
            }
        }
        float qiH[4], qaH[4];
        *(float4*)(qiH) = *(const float4*)(g_qinv + 256 + 4 * lane);
        *(float4*)(qaH) = *(const float4*)(g_qadd + 256 + 4 * lane);
#pragma unroll
        for (int jj = 0; jj < 4; jj++) {
            float v = 0.0f;
#pragma unroll
            for (int t = 0; t < T_; t++) {
                __nv_bfloat162 pr = acc[t][4 + (jj >> 1)];
                float qf = (jj & 1) ? __high2float(pr) : __low2float(pr);
                float qn = fmaf(qf, qiH[jj], qaH[jj]);
                float h = v + (qn - v) * 0.5f;
                bool s = (h >= 1.0f);
                v = s ? 0.0f : h;
                smask[t] |= (s ? 1u : 0u) << (8 + jj);
            }
        }
    }

    // ---- phase 2b: attn AND, one guarded region per t ----
    unsigned rmask[T_];
#pragma unroll
    for (int t = 0; t < T_; t++) {
        rmask[t] = 0u;
        if (__any_sync(0xffffffffu, smask[t] != 0u)) {
            unsigned sm = smask[t];
            const size_t base_t = (((size_t)t * B_ + b) * C_) * (size_t)N_ + n;
            while (sm) {
                int j = __ffs((int)sm) - 1;
                sm &= sm - 1;
                int o = (j < 8) ? (8 * lane + j) : (256 + 4 * lane + (j - 8));
                size_t idx = base_t + (size_t)o * N_;
                if (ak[idx] && av[idx]) rmask[t] |= 1u << j;
            }
        }
    }

    // ---- per t: phase 3 (usually skipped), epilogue bn, stage, flush ----
#pragma unroll 1
    for (int t = 0; t < T_; t++) {
        float oa[12];
#pragma unroll
        for (int j = 0; j < 12; j++) oa[j] = 0.0f;

        if (__any_sync(0xffffffffu, rmask[t] != 0u)) {
#pragma unroll 1
            for (int wbit = 0; wbit < 12; wbit++) {
                unsigned mb = __ballot_sync(0xffffffffu, (rmask[t] >> wbit) & 1u);
                while (mb) {
                    int l2 = __ffs((int)mb) - 1;
                    mb &= mb - 1;
                    int c = (wbit < 8) ? (8 * l2 + wbit) : (256 + 4 * l2 + (wbit - 8));
                    const float* row = g_wpT + c * C_;
                    float4 w0 = *(const float4*)(row + 8 * lane);
                    float4 w1 = *(const float4*)(row + 8 * lane + 4);
                    float4 w2 = *(const float4*)(row + 256 + 4 * lane);
                    oa[0] += w0.x; oa[1] += w0.y; oa[2]  += w0.z; oa[3]  += w0.w;
                    oa[4] += w1.x; oa[5] += w1.y; oa[6]  += w1.z; oa[7]  += w1.w;
                    oa[8] += w2.x; oa[9] += w2.y; oa[10] += w2.z; oa[11] += w2.w;
                }
            }
        }

        // epilogue: y = oa*pinv + pc, staged as [j=warp][o]
        {
            const int o0 = 8 * lane;
            float4 piA = *(const float4*)(g_pinv + o0);
            float4 piB = *(const float4*)(g_pinv + o0 + 4);
            float4 pcA = *(const float4*)(g_pc + o0);
            float4 pcB = *(const float4*)(g_pc + o0 + 4);
            float4 y0, y1;
            y0.x = oa[0] * piA.x + pcA.x;  y0.y = oa[1] * piA.y + pcA.y;
            y0.z = oa[2] * piA.z + pcA.z;  y0.w = oa[3] * piA.w + pcA.w;
            y1.x = oa[4] * piB.x + pcB.x;  y1.y = oa[5] * piB.y + pcB.y;
            y1.z = oa[6] * piB.z + pcB.z;  y1.w = oa[7] * piB.w + pcB.w;
            float* sp = stage + warp * C_ + o0;
            *(float4*)sp = y0;
            *(float4*)(sp + 4) = y1;

            const int o1 = 256 + 4 * lane;
            float4 piC = *(const float4*)(g_pinv + o1);
            float4 pcC = *(const float4*)(g_pc + o1);
            float4 z0;
            z0.x = oa[8]  * piC.x + pcC.x;  z0.y = oa[9]  * piC.y + pcC.y;
            z0.z = oa[10] * piC.z + pcC.z;  z0.w = oa[11] * piC.w + pcC.w;
            *(float4*)(stage + warp * C_ + o1) = z0;
        }

        // flush t: stage[j][o] -> out[t][b][o][n0..n0+8)
        __syncthreads();
        for (int o = tid; o < C_; o += 256) {
            const float* sp = stage + o;
            float4 u, w;
            u.x = sp[0 * C_]; u.y = sp[1 * C_]; u.z = sp[2 * C_]; u.w = sp[3 * C_];
            w.x = sp[4 * C_]; w.y = sp[5 * C_]; w.z = sp[6 * C_]; w.w = sp[7 * C_];
            float* dst = out + (((size_t)t * B_ + b) * C_ + o) * (size_t)N_ + n0;
            *(float4*)dst = u;
            *(float4*)(dst + 4) = w;
        }
        __syncthreads();
    }
}

// ---------------- launch ----------------
extern "C" void kernel_launch(void* const* d_in, const int* in_sizes, int n_in,
                              void* d_out, int out_size) {
    const float*         x  = (const float*)d_in[0];
    const unsigned char* ak = (const unsigned char*)d_in[1];
    const unsigned char* av = (const unsigned char*)d_in[2];
    const float*         wq = (const float*)d_in[3];
    const float*         qg = (const float*)d_in[4];
    const float*         qb = (const float*)d_in[5];
    const float*         qm = (const float*)d_in[6];
    const float*         qv = (const float*)d_in[7];
    const float*         wp = (const float*)d_in[8];
    const float*         bp = (const float*)d_in[9];
    const float*         pg = (const float*)d_in[10];
    const float*         pb = (const float*)d_in[11];
    const float*         pm = (const float*)d_in[12];
    const float*         pv = (const float*)d_in[13];
    float* out = (float*)d_out;

    (void)in_sizes; (void)n_in; (void)out_size;

    k_front<<<LP_BLOCKS + PREP_BLOCKS, 256>>>(x, wq, wp, qg, qb, qm, qv, pg, pb, pm, pv, bp);
    k_main<<<B_ * 128, 256>>>(ak, av, out);
}

// round 15
// speedup vs baseline: 1.1788x; 1.0918x over previous
#include <cuda_runtime.h>
#include <cuda_bf16.h>
#include <cstdint>

#define T_ 4
#define B_ 16
#define C_ 384
#define N_ 1024
#define TB_STRIDE (B_*C_*N_)

#define A_TILE 98304                    // 128 rows x 768 B (bf16, swizzled)
#define SM_A 0
#define SM_STAGE 0                      // 384*33*4 = 50688, overlaps A after MMAs
#define SM_BPACK (A_TILE)               // 24*32*2 u32 = 6144 B
#define SM_PMASK (A_TILE + 6144)        // 4*32*12 u32 = 6144 B
#define SM_TOTAL (A_TILE + 6144 + 6144) // 110592 B -> 2 blocks/SM

// ---------------- scratch (device globals; no allocation) ----------------
__device__ unsigned g_mask[(size_t)T_*B_*N_*12];                // 3 MB channel masks
__device__ __align__(16) unsigned char g_wqR[3 * A_TILE];       // wq bf16, ldmatrix-swizzled
__device__ __align__(16) float g_wpT[C_*C_];                    // wpT[c][o] fp32
__device__ __align__(16) float g_qinv[C_], g_qadd[C_], g_pinv[C_], g_pc[C_];

__device__ __forceinline__ uint32_t s2u32(const void* p) {
    uint32_t a;
    asm("{ .reg .u64 t; cvta.to.shared.u64 t, %1; cvt.u32.u64 %0, t; }" : "=r"(a) : "l"(p));
    return a;
}
__device__ __forceinline__ void ldm4(unsigned* r, uint32_t a) {
    asm volatile("ldmatrix.sync.aligned.m8n8.x4.shared.b16 {%0,%1,%2,%3}, [%4];"
                 : "=r"(r[0]), "=r"(r[1]), "=r"(r[2]), "=r"(r[3]) : "r"(a));
}
__device__ __forceinline__ void mma16816(float* d, const unsigned* a, unsigned b0, unsigned b1) {
    asm volatile("mma.sync.aligned.m16n8k16.row.col.f32.bf16.bf16.f32 "
                 "{%0,%1,%2,%3}, {%4,%5,%6,%7}, {%8,%9}, {%0,%1,%2,%3};"
                 : "+f"(d[0]), "+f"(d[1]), "+f"(d[2]), "+f"(d[3])
                 : "r"(a[0]), "r"(a[1]), "r"(a[2]), "r"(a[3]), "r"(b0), "r"(b1));
}

// ---------------- K0+K1: LIF-pack (0..767) + weight-prep (768..1343) ----------------
#define LP_BLOCKS 768          // (N/256=4) * (C/32=12) * B=16
#define PREP_BLOCKS 576        // C*C / 256

__global__ void __launch_bounds__(256) k_front(
    const float* __restrict__ x,
    const float* __restrict__ wq, const float* __restrict__ wp,
    const float* __restrict__ qg, const float* __restrict__ qb,
    const float* __restrict__ qm, const float* __restrict__ qv,
    const float* __restrict__ pg, const float* __restrict__ pb,
    const float* __restrict__ pm, const float* __restrict__ pv,
    const float* __restrict__ bp)
{
    const int bx = blockIdx.x;
    if (bx < LP_BLOCKS) {
        const int nq = bx & 3;
        const int cy = (bx >> 2) % 12;
        const int b  = bx / 48;
        const int n  = nq * 256 + threadIdx.x;
        const int c0 = cy * 32;

        unsigned m[T_];
#pragma unroll
        for (int t = 0; t < T_; t++) m[t] = 0u;

#pragma unroll 4
        for (int k = 0; k < 32; k++) {
            const float* px = x + ((size_t)b * C_ + c0 + k) * N_ + n;
            float v = 0.f;
#pragma unroll
            for (int t = 0; t < T_; t++) {
                float xt = px[(size_t)t * TB_STRIDE];
                float h = v + (xt - v) * 0.5f;
                bool  s = (h >= 1.0f);
                v = s ? 0.f : h;
                m[t] |= (s ? 1u : 0u) << k;
            }
        }

#pragma unroll
        for (int t = 0; t < T_; t++)
            g_mask[(((size_t)t * B_ + b) * N_ + n) * 12 + cy] = m[t];
    } else {
        int i = (bx - LP_BLOCKS) * 256 + threadIdx.x;   // i = o*C + c
        if (i < C_ * C_) {
            int o = i / C_;
            int c = i - o * C_;
            g_wpT[c * C_ + o] = wp[i];
            // ldmatrix-swizzled A image: tile = o>>7, row = o&127, byte = (c*2) ^ ((row&7)<<4)
            int tile = o >> 7, row = o & 127;
            unsigned boff = (unsigned)((c * 2) ^ ((row & 7) << 4));
            *(__nv_bfloat16*)(g_wqR + tile * A_TILE + row * 768 + boff) = __float2bfloat16(wq[i]);
        }
        if (i < C_) {
            float iv = qg[i] / sqrtf(qv[i] + 1e-5f);
            g_qinv[i] = iv;
            g_qadd[i] = qb[i] - qm[i] * iv;
            float iv2 = pg[i] / sqrtf(pv[i] + 1e-5f);
            g_pinv[i] = iv2;
            g_pc[i]   = pb[i] - pm[i] * iv2 + bp[i] * iv2;
        }
    }
}

// ---------------- K2: HMMA dense q-GEMM + fused LIF/attn/proj epilogue ----------------
// block = (b, n-tile of 32); 256 threads = 8 warps; grid 512.
// warp = (mhalf = warp>>2, nt = warp&3): owns 4 m16-tiles x 1 n8-tile x 4 t.
__global__ void __launch_bounds__(256, 2) k_mma(
    const unsigned char* __restrict__ ak, const unsigned char* __restrict__ av,
    float* __restrict__ out)
{
    extern __shared__ char sm[];
    const uint32_t smb = s2u32(sm);
    unsigned* bpack = (unsigned*)(sm + SM_BPACK);   // [ks][lane][2]
    unsigned* pmask = (unsigned*)(sm + SM_PMASK);   // [t][n][12]
    float*    stg   = (float*)(sm + SM_STAGE);      // [o][33]

    const int tile = blockIdx.x & 31;
    const int b    = blockIdx.x >> 5;
    const int n0   = tile * 32;
    const int tid  = threadIdx.x;
    const int lane = tid & 31;
    const int warp = tid >> 5;
    const int gid  = lane >> 2;
    const int tig  = lane & 3;
    const int mhalf = warp >> 2;
    const int nt    = warp & 3;

    // ---- zero pmask + precompute B-fragment bit pack ----
    for (int i = tid; i < T_ * 32 * 12; i += 256) pmask[i] = 0u;

    for (int e = tid; e < 24 * 32; e += 256) {
        int ks = e >> 5, L = e & 31;
        int nL = L >> 2;
        int c0 = ks * 16 + (L & 3) * 2;
        int wi = c0 >> 5, sh = c0 & 31;     // sh <= 22, so sh+9 <= 31: no word crossing
        unsigned w0 = 0u, w1 = 0u;
#pragma unroll
        for (int t = 0; t < T_; t++) {
#pragma unroll
            for (int ntl = 0; ntl < 4; ntl++) {
                int n = ntl * 8 + nL;
                unsigned word = g_mask[(((size_t)t * B_ + b) * N_ + n0 + n) * 12 + wi];
                unsigned bits = word >> sh;
                unsigned f2 = (unsigned)(8 * ntl + 2 * t);
                w0 |= (bits & 3u) << f2;
                w1 |= ((bits >> 8) & 3u) << f2;
            }
        }
        bpack[e * 2 + 0] = w0;
        bpack[e * 2 + 1] = w1;
    }

    bool had = false;

    // ldmatrix per-lane addressing: i = lane>>3 selects 8x8 quadrant, r = lane&7 row
    const int li = lane >> 3, lr = lane & 7;
    const uint32_t rowoff = (uint32_t)(((mhalf * 4) * 16 + (li & 1) * 8 + lr) * 768);

#pragma unroll 1
    for (int mph = 0; mph < 3; mph++) {
        __syncthreads();   // prior A-smem reads (and bpack writes on mph==0) complete
        {
            const uint4* src = (const uint4*)(g_wqR + mph * A_TILE);
            uint4* dst = (uint4*)(sm + SM_A);
            for (int i = tid; i < A_TILE / 16; i += 256) dst[i] = src[i];
        }
        __syncthreads();

        float D[4][4][4];
#pragma unroll
        for (int mi = 0; mi < 4; mi++)
#pragma unroll
            for (int t = 0; t < 4; t++)
#pragma unroll
                for (int q = 0; q < 4; q++) D[mi][t][q] = 0.f;

#pragma unroll 1
        for (int ks = 0; ks < 24; ks++) {
            unsigned A[4][4];
            uint32_t colb = ((uint32_t)(ks * 32 + (li >> 1) * 16)) ^ ((uint32_t)lr << 4);
#pragma unroll
            for (int mi = 0; mi < 4; mi++)
                ldm4(A[mi], smb + SM_A + rowoff + (uint32_t)(mi * 16 * 768) + colb);

            uint2 pk = *(const uint2*)(bpack + (ks * 32 + lane) * 2);
#pragma unroll
            for (int t = 0; t < 4; t++) {
                unsigned sh = (unsigned)(8 * nt + 2 * t);
                unsigned x0 = (pk.x >> sh) & 3u;
                unsigned x1 = (pk.y >> sh) & 3u;
                unsigned b0 = ((x0 & 1u) * 0x3F80u) | (((x0 >> 1) & 1u) * 0x3F800000u);
                unsigned b1 = ((x1 & 1u) * 0x3F80u) | (((x1 >> 1) & 1u) * 0x3F800000u);
#pragma unroll
                for (int mi = 0; mi < 4; mi++)
                    mma16816(D[mi][t], A[mi], b0, b1);
            }
        }

        // ---- pass A: branch-free LIF on D fragments -> spike bits ----
        unsigned sb[T_] = {0u, 0u, 0u, 0u};
#pragma unroll
        for (int mi = 0; mi < 4; mi++) {
#pragma unroll
            for (int h = 0; h < 2; h++) {
                int o = mph * 128 + (mhalf * 4 + mi) * 16 + h * 8 + gid;
                float qi = g_qinv[o], qa = g_qadd[o];
#pragma unroll
                for (int cp = 0; cp < 2; cp++) {
                    float v = 0.f;
#pragma unroll
                    for (int t = 0; t < 4; t++) {
                        float qn = fmaf(D[mi][t][h * 2 + cp], qi, qa);
                        float hh = v + (qn - v) * 0.5f;
                        bool s = (hh >= 1.0f);
                        v = s ? 0.f : hh;
                        sb[t] |= (s ? 1u : 0u) << (mi * 4 + h * 2 + cp);
                    }
                }
            }
        }
#pragma unroll
        for (int t = 0; t < T_; t++) {
            if (__any_sync(0xffffffffu, sb[t] != 0u)) {
                unsigned m = sb[t];
                while (m) {
                    int idx = __ffs((int)m) - 1;
                    m &= m - 1;
                    int mi = idx >> 2, h = (idx >> 1) & 1, cp = idx & 1;
                    int o = mph * 128 + (mhalf * 4 + mi) * 16 + h * 8 + gid;
                    int n = nt * 8 + tig * 2 + cp;
                    size_t g = (((size_t)t * B_ + b) * C_ + o) * (size_t)N_ + n0 + n;
                    if (ak[g] && av[g]) {
                        atomicOr(&pmask[(t * 32 + n) * 12 + (o >> 5)], 1u << (o & 31));
                        had = true;
                    }
                }
            }
        }
    }

    int nspk = __syncthreads_count(had ? 1 : 0);

    // ---- pass B: sparse proj + bn, staged coalesced output (stage overlaps A) ----
#pragma unroll 1
    for (int t = 0; t < T_; t++) {
#pragma unroll 1
        for (int rep = 0; rep < 2; rep++) {
            if (rep == 0 || tid >= 128) {
                int o = (rep == 0) ? tid : tid + 128;
                float pi = g_pinv[o], pcn = g_pc[o];
                if (nspk == 0) {
                    for (int j = 0; j < 32; j++) stg[o * 33 + j] = pcn;
                } else {
                    for (int j = 0; j < 32; j++) {
                        float oa = 0.f;
#pragma unroll
                        for (int w = 0; w < 12; w++) {
                            unsigned mw = pmask[(t * 32 + j) * 12 + w];
                            while (mw) {
                                int k = __ffs((int)mw) - 1;
                                mw &= mw - 1;
                                oa += g_wpT[(w * 32 + k) * C_ + o];
                            }
                        }
                        stg[o * 33 + j] = fmaf(oa, pi, pcn);
                    }
                }
            }
        }
        __syncthreads();
        for (int q = tid; q < 384 * 8; q += 256) {
            int orow = q >> 3, j4 = (q & 7) * 4;
            float4 u;
            u.x = stg[orow * 33 + j4 + 0];
            u.y = stg[orow * 33 + j4 + 1];
            u.z = stg[orow * 33 + j4 + 2];
            u.w = stg[orow * 33 + j4 + 3];
            *(float4*)(out + (((size_t)t * B_ + b) * C_ + orow) * (size_t)N_ + n0 + j4) = u;
        }
        __syncthreads();
    }
}

// ---------------- launch ----------------
extern "C" void kernel_launch(void* const* d_in, const int* in_sizes, int n_in,
                              void* d_out, int out_size) {
    const float*         x  = (const float*)d_in[0];
    const unsigned char* ak = (const unsigned char*)d_in[1];
    const unsigned char* av = (const unsigned char*)d_in[2];
    const float*         wq = (const float*)d_in[3];
    const float*         qg = (const float*)d_in[4];
    const float*         qb = (const float*)d_in[5];
    const float*         qm = (const float*)d_in[6];
    const float*         qv = (const float*)d_in[7];
    const float*         wp = (const float*)d_in[8];
    const float*         bp = (const float*)d_in[9];
    const float*         pg = (const float*)d_in[10];
    const float*         pb = (const float*)d_in[11];
    const float*         pm = (const float*)d_in[12];
    const float*         pv = (const float*)d_in[13];
    float* out = (float*)d_out;

    (void)in_sizes; (void)n_in; (void)out_size;

    static int configured = 0;
    if (!configured) {
        cudaFuncSetAttribute(k_mma, cudaFuncAttributeMaxDynamicSharedMemorySize, SM_TOTAL);
        configured = 1;
    }

    k_front<<<LP_BLOCKS + PREP_BLOCKS, 256>>>(x, wq, wp, qg, qb, qm, qv, pg, pb, pm, pv, bp);
    k_mma<<<B_ * 32, 256, SM_TOTAL>>>(ak, av, out);
}